// round 1
// baseline (speedup 1.0000x reference)
#include <cuda_runtime.h>
#include <cstdint>

#define TT 512
#define BB 1024
#define VV 64
#define HH 100
#define H3 300
#define ROWS 8
#define NBLK (BB / ROWS)          // 128
#define RTHREADS 320

// ---- shared memory layout (floats) for recurrent kernel ----
#define OFF_WX 0                  // [64][300]  W_ih transposed: Wx[v][c]
#define OFF_WH 19200              // [100][300] W_hh transposed: Wh[k][c]
#define OFF_XS 49200              // [2][64][8] x tile, double buffered: xs[buf][v][r]
#define OFF_HS 50224              // [100][8]   hidden: hs[j][r]
#define OFF_GS 51024              // [300][8]   gate preact (r,z: x+h combined; n: x part)
#define OFF_GN 53424              // [100][8]   h-part of n gate
#define OFF_BI 54224              // [300] (+pad 4)
#define OFF_BH 54528              // [300] (+pad 4)
#define OFF_LEN 54832             // 8 ints
#define SMEM_FLOATS (OFF_LEN + 8)
#define SMEM_BYTES (SMEM_FLOATS * 4)

// scratch: hidden states for all (t, b): 512*1024*100 floats = 210 MB
__device__ float g_hidden[(size_t)TT * BB * HH];

__device__ __forceinline__ float sigmoid_f(float x) {
    return 1.0f / (1.0f + __expf(-x));
}

__global__ void __launch_bounds__(RTHREADS, 1)
gru_recurrent_kernel(const float* __restrict__ x,
                     const float* __restrict__ h0,
                     const int*   __restrict__ lengths,
                     const float* __restrict__ W_ih,
                     const float* __restrict__ W_hh,
                     const float* __restrict__ b_ih,
                     const float* __restrict__ b_hh) {
    extern __shared__ float sm[];
    int* len_s = (int*)(sm + OFF_LEN);
    const int tid = threadIdx.x;
    const int row0 = blockIdx.x * ROWS;

    // ---- one-time loads into SMEM ----
    // W_ih [300][64] -> Wx[v*300 + c]
    for (int e = tid; e < H3 * VV; e += RTHREADS) {
        int c = e >> 6, v = e & 63;
        sm[OFF_WX + v * H3 + c] = W_ih[e];
    }
    // W_hh [300][100] -> Wh[k*300 + c]
    for (int e = tid; e < H3 * HH; e += RTHREADS) {
        int c = e / 100, k = e - c * 100;
        sm[OFF_WH + k * H3 + c] = W_hh[e];
    }
    for (int e = tid; e < H3; e += RTHREADS) {
        sm[OFF_BI + e] = b_ih[e];
        sm[OFF_BH + e] = b_hh[e];
    }
    // h init: h0 [B][100] -> hs[j*8 + r]
    for (int e = tid; e < ROWS * HH; e += RTHREADS) {
        int r = e / 100, j = e - r * 100;
        sm[OFF_HS + j * ROWS + r] = h0[(size_t)(row0 + r) * HH + j];
    }
    if (tid < ROWS) len_s[tid] = lengths[row0 + tid];
    // x tile for t=0 into buffer 0: xs[v*8 + r]
    {
        int e0 = tid;
        sm[OFF_XS + (e0 & 63) * ROWS + (e0 >> 6)] =
            x[((size_t)0 * BB + row0 + (e0 >> 6)) * VV + (e0 & 63)];
        if (tid < 192) {
            int e1 = tid + RTHREADS;
            sm[OFF_XS + (e1 & 63) * ROWS + (e1 >> 6)] =
                x[((size_t)0 * BB + row0 + (e1 >> 6)) * VV + (e1 & 63)];
        }
    }
    __syncthreads();

    int ml = len_s[0];
#pragma unroll
    for (int i = 1; i < ROWS; i++) ml = max(ml, len_s[i]);

    const int c = tid;
    const float* WXc = sm + OFF_WX + c;
    const float* WHc = sm + OFF_WH + c;

    for (int t = 0; t < ml; t++) {
        const int buf = t & 1;
        const int nbuf = buf ^ 1;
        const bool pf = (t + 1 < ml);
        float px0 = 0.0f, px1 = 0.0f;
        if (pf) {
            int e0 = tid;
            px0 = x[((size_t)(t + 1) * BB + row0 + (e0 >> 6)) * VV + (e0 & 63)];
            if (tid < 192) {
                int e1 = tid + RTHREADS;
                px1 = x[((size_t)(t + 1) * BB + row0 + (e1 >> 6)) * VV + (e1 & 63)];
            }
        }

        // ---- compute phase: g[c][r] for c in [0,300) ----
        if (c < H3) {
            float accA[ROWS];
            float accB[ROWS];
#pragma unroll
            for (int r = 0; r < ROWS; r++) { accA[r] = 0.0f; accB[r] = 0.0f; }

            const float* xsb = sm + OFF_XS + buf * (VV * ROWS);
#pragma unroll 4
            for (int v = 0; v < VV; v++) {
                float w = WXc[v * H3];
                float4 p = *(const float4*)(xsb + v * ROWS);
                float4 q = *(const float4*)(xsb + v * ROWS + 4);
                accA[0] = fmaf(w, p.x, accA[0]);
                accA[1] = fmaf(w, p.y, accA[1]);
                accA[2] = fmaf(w, p.z, accA[2]);
                accA[3] = fmaf(w, p.w, accA[3]);
                accA[4] = fmaf(w, q.x, accA[4]);
                accA[5] = fmaf(w, q.y, accA[5]);
                accA[6] = fmaf(w, q.z, accA[6]);
                accA[7] = fmaf(w, q.w, accA[7]);
            }
            const float* hsb = sm + OFF_HS;
#pragma unroll 4
            for (int k = 0; k < HH; k++) {
                float w = WHc[k * H3];
                float4 p = *(const float4*)(hsb + k * ROWS);
                float4 q = *(const float4*)(hsb + k * ROWS + 4);
                accB[0] = fmaf(w, p.x, accB[0]);
                accB[1] = fmaf(w, p.y, accB[1]);
                accB[2] = fmaf(w, p.z, accB[2]);
                accB[3] = fmaf(w, p.w, accB[3]);
                accB[4] = fmaf(w, q.x, accB[4]);
                accB[5] = fmaf(w, q.y, accB[5]);
                accB[6] = fmaf(w, q.z, accB[6]);
                accB[7] = fmaf(w, q.w, accB[7]);
            }
            float* gsc = sm + OFF_GS + c * ROWS;
            if (c < 2 * HH) {
#pragma unroll
                for (int r = 0; r < ROWS; r++) gsc[r] = accA[r] + accB[r];
            } else {
                float* gnc = sm + OFF_GN + (c - 2 * HH) * ROWS;
#pragma unroll
                for (int r = 0; r < ROWS; r++) { gsc[r] = accA[r]; gnc[r] = accB[r]; }
            }
        }

        // stash prefetched x tile into the other buffer (visible after barrier)
        if (pf) {
            int e0 = tid;
            sm[OFF_XS + nbuf * (VV * ROWS) + (e0 & 63) * ROWS + (e0 >> 6)] = px0;
            if (tid < 192) {
                int e1 = tid + RTHREADS;
                sm[OFF_XS + nbuf * (VV * ROWS) + (e1 & 63) * ROWS + (e1 >> 6)] = px1;
            }
        }
        __syncthreads();

        // ---- gate phase: 800 outputs (r, j) ----
        for (int o = tid; o < ROWS * HH; o += RTHREADS) {
            int r = o / 100;
            int j = o - r * 100;
            float g_r = sm[OFF_GS + j * ROWS + r]            + sm[OFF_BI + j]       + sm[OFF_BH + j];
            float g_z = sm[OFF_GS + (j + 100) * ROWS + r]    + sm[OFF_BI + j + 100] + sm[OFF_BH + j + 100];
            float gxn = sm[OFF_GS + (j + 200) * ROWS + r]    + sm[OFF_BI + j + 200];
            float ghn = sm[OFF_GN + j * ROWS + r]            + sm[OFF_BH + j + 200];
            float rg = sigmoid_f(g_r);
            float zg = sigmoid_f(g_z);
            float nv = tanhf(fmaf(rg, ghn, gxn));
            float hold = sm[OFF_HS + j * ROWS + r];
            float hnew = fmaf(zg, hold - nv, nv);   // (1-z)n + z h
            float hout = (t < len_s[r]) ? hnew : hold;
            sm[OFF_HS + j * ROWS + r] = hout;
            g_hidden[((size_t)t * BB + row0 + r) * HH + j] = hout;
        }
        __syncthreads();
    }
}

// ---- epilogue: logits + log_softmax + mask ----
__global__ void __launch_bounds__(256)
gru_output_kernel(const int*   __restrict__ lengths,
                  const float* __restrict__ W_out,
                  const float* __restrict__ b_out,
                  float*       __restrict__ out) {
    __shared__ float Wo[HH * VV];   // Wo[k*64 + c]
    __shared__ float bo[VV];
    __shared__ float hrow[8][HH];
    const int tid = threadIdx.x;
    for (int e = tid; e < VV * HH; e += 256) {
        int cc = e / 100, k = e - cc * 100;
        Wo[k * VV + cc] = W_out[e];
    }
    if (tid < VV) bo[tid] = b_out[tid];
    __syncthreads();

    const int w = tid >> 5;
    const int lane = tid & 31;
    const int nrg = (TT * BB) / 8;

    for (int rg = blockIdx.x; rg < nrg; rg += gridDim.x) {
        int rowid = rg * 8 + w;
        int t = rowid >> 10;          // /1024
        int b = rowid & 1023;
        int L = lengths[b];
        float* op = out + (size_t)rowid * VV;
        if (t >= L) {
            op[lane] = 0.0f;
            op[lane + 32] = 0.0f;
            continue;
        }
        const float* hp = g_hidden + (size_t)rowid * HH;
        hrow[w][lane]      = hp[lane];
        hrow[w][lane + 32] = hp[lane + 32];
        hrow[w][lane + 64] = hp[lane + 64];
        if (lane < 4) hrow[w][lane + 96] = hp[lane + 96];
        __syncwarp();
        float a0 = 0.0f, a1 = 0.0f;
#pragma unroll 4
        for (int k = 0; k < HH; k++) {
            float hk = hrow[w][k];
            a0 = fmaf(hk, Wo[k * VV + lane], a0);
            a1 = fmaf(hk, Wo[k * VV + lane + 32], a1);
        }
        float l0 = a0 + bo[lane];
        float l1 = a1 + bo[lane + 32];
        float m = fmaxf(l0, l1);
#pragma unroll
        for (int s = 16; s; s >>= 1) m = fmaxf(m, __shfl_xor_sync(0xffffffffu, m, s));
        float se = __expf(l0 - m) + __expf(l1 - m);
#pragma unroll
        for (int s = 16; s; s >>= 1) se += __shfl_xor_sync(0xffffffffu, se, s);
        float lse = m + __logf(se);
        op[lane]      = l0 - lse;
        op[lane + 32] = l1 - lse;
        __syncwarp();
    }
}

extern "C" void kernel_launch(void* const* d_in, const int* in_sizes, int n_in,
                              void* d_out, int out_size) {
    const float* x      = (const float*)d_in[0];
    const float* h0     = (const float*)d_in[1];
    const int*   lens   = (const int*)  d_in[2];
    const float* W_ih   = (const float*)d_in[3];
    const float* W_hh   = (const float*)d_in[4];
    const float* b_ih   = (const float*)d_in[5];
    const float* b_hh   = (const float*)d_in[6];
    const float* W_out  = (const float*)d_in[7];
    const float* b_out  = (const float*)d_in[8];
    float* out = (float*)d_out;

    cudaFuncSetAttribute(gru_recurrent_kernel,
                         cudaFuncAttributeMaxDynamicSharedMemorySize, SMEM_BYTES);

    gru_recurrent_kernel<<<NBLK, RTHREADS, SMEM_BYTES>>>(
        x, h0, lens, W_ih, W_hh, b_ih, b_hh);
    gru_output_kernel<<<2048, 256>>>(lens, W_out, b_out, out);
}

// round 2
// speedup vs baseline: 1.1437x; 1.1437x over previous
#include <cuda_runtime.h>
#include <cstdint>

#define TT 512
#define BB 1024
#define VV 64
#define HH 100
#define H3 300
#define ROWS 8
#define NBLK (BB / ROWS)          // 128
#define RTHREADS 640

// ---- shared memory layout (floats) ----
#define OFF_WX 0                  // [64][300]  W_ih transposed: Wx[v*300+c]
#define OFF_WH 19200              // [100][300] W_hh transposed: Wh[k*300+c]
#define OFF_XS 49200              // [2][64][8] x tile double buffered: xs[buf*512+v*8+r]
#define OFF_HS 50224              // [100][8]   hidden (dot layout): hs[k*8+r]
#define OFF_H2 51024              // [8][100]   hidden (gate layout): h2[r*100+j]
#define OFF_GX 51824              // [8][300]   x-part partials gX[r*300+c]
#define OFF_GH 54224              // [8][300]   h-part partials gH[r*300+c]
#define OFF_BRZ 56624             // [200] b_ih+b_hh for r,z
#define OFF_BIN 56824             // [100] b_ih n-gate
#define OFF_BHN 56924             // [100] b_hh n-gate
#define OFF_LEN 57024             // 8 ints
#define SMEM_FLOATS (OFF_LEN + 8)
#define SMEM_BYTES (SMEM_FLOATS * 4)   // 228,128 B <= 232,448 max dynamic

// scratch: hidden states for all (t, b): 512*1024*100 floats = 210 MB
__device__ float g_hidden[(size_t)TT * BB * HH];

__device__ __forceinline__ float sigmoid_f(float x) {
    return 1.0f / (1.0f + __expf(-x));
}

typedef unsigned long long u64;

__device__ __forceinline__ u64 splat2(float w) {
    u64 r;
    asm("mov.b64 %0, {%1, %1};" : "=l"(r) : "f"(w));
    return r;
}
__device__ __forceinline__ u64 fma2(u64 a, u64 b, u64 c) {
    u64 d;
    asm("fma.rn.f32x2 %0, %1, %2, %3;" : "=l"(d) : "l"(a), "l"(b), "l"(c));
    return d;
}
__device__ __forceinline__ void unpk(u64 v, float& lo, float& hi) {
    asm("mov.b64 {%0, %1}, %2;" : "=f"(lo), "=f"(hi) : "l"(v));
}

__global__ void __launch_bounds__(RTHREADS, 1)
gru_recurrent_kernel(const float* __restrict__ x,
                     const float* __restrict__ h0,
                     const int*   __restrict__ lengths,
                     const float* __restrict__ W_ih,
                     const float* __restrict__ W_hh,
                     const float* __restrict__ b_ih,
                     const float* __restrict__ b_hh) {
    extern __shared__ float sm[];
    int* len_s = (int*)(sm + OFF_LEN);
    const int tid = threadIdx.x;
    const int row0 = blockIdx.x * ROWS;

    // ---- one-time loads ----
    for (int e = tid; e < H3 * VV; e += RTHREADS) {
        int c = e >> 6, v = e & 63;
        sm[OFF_WX + v * H3 + c] = W_ih[e];
    }
    for (int e = tid; e < H3 * HH; e += RTHREADS) {
        int c = e / 100, k = e - c * 100;
        sm[OFF_WH + k * H3 + c] = W_hh[e];
    }
    for (int e = tid; e < 200; e += RTHREADS) sm[OFF_BRZ + e] = b_ih[e] + b_hh[e];
    if (tid < 100) {
        sm[OFF_BIN + tid] = b_ih[200 + tid];
        sm[OFF_BHN + tid] = b_hh[200 + tid];
    }
    for (int e = tid; e < ROWS * HH; e += RTHREADS) {
        int r = e / 100, j = e - r * 100;
        float hv = h0[(size_t)(row0 + r) * HH + j];
        sm[OFF_HS + j * ROWS + r] = hv;
        sm[OFF_H2 + r * HH + j]   = hv;
    }
    if (tid < ROWS) len_s[tid] = lengths[row0 + tid];
    // t=0 x tile into buffer 0: xs[v*8+r]
    if (tid < 256) {
        int e = tid * 2;
        int r = e >> 6, v = e & 63;
        float2 px = *(const float2*)&x[((size_t)0 * BB + row0 + r) * VV + v];
        sm[OFF_XS + v * ROWS + r]       = px.x;
        sm[OFF_XS + (v + 1) * ROWS + r] = px.y;
    }
    __syncthreads();

    int ml = len_s[0];
#pragma unroll
    for (int i = 1; i < ROWS; i++) ml = max(ml, len_s[i]);

    const bool isX = (tid < H3);
    const bool isH = (tid >= 320) && (tid < 320 + H3);
    const int  c   = isX ? tid : (tid - 320);

    for (int t = 0; t < ml; t++) {
        const int buf = t & 1;
        const int nbuf = buf ^ 1;
        const bool pf = (t + 1 < ml) && (tid < 256);
        float2 px;
        int pv = 0, pr = 0;
        if (pf) {
            int e = tid * 2;
            pr = e >> 6; pv = e & 63;
            px = *(const float2*)&x[((size_t)(t + 1) * BB + row0 + pr) * VV + pv];
        }

        if (isX) {
            // x-part: 64 iters
            const float* WXc = sm + OFF_WX + c;
            const float* xsb = sm + OFF_XS + buf * (VV * ROWS);
            u64 a0 = 0, a1 = 0, a2 = 0, a3 = 0;
#pragma unroll 8
            for (int v = 0; v < VV; v++) {
                u64 w2 = splat2(WXc[v * H3]);
                ulonglong2 p = *(const ulonglong2*)(xsb + v * ROWS);
                ulonglong2 q = *(const ulonglong2*)(xsb + v * ROWS + 4);
                a0 = fma2(w2, p.x, a0);
                a1 = fma2(w2, p.y, a1);
                a2 = fma2(w2, q.x, a2);
                a3 = fma2(w2, q.y, a3);
            }
            float f0, f1;
            unpk(a0, f0, f1); sm[OFF_GX + 0 * H3 + c] = f0; sm[OFF_GX + 1 * H3 + c] = f1;
            unpk(a1, f0, f1); sm[OFF_GX + 2 * H3 + c] = f0; sm[OFF_GX + 3 * H3 + c] = f1;
            unpk(a2, f0, f1); sm[OFF_GX + 4 * H3 + c] = f0; sm[OFF_GX + 5 * H3 + c] = f1;
            unpk(a3, f0, f1); sm[OFF_GX + 6 * H3 + c] = f0; sm[OFF_GX + 7 * H3 + c] = f1;
        } else if (isH) {
            // h-part: 100 iters
            const float* WHc = sm + OFF_WH + c;
            const float* hsb = sm + OFF_HS;
            u64 a0 = 0, a1 = 0, a2 = 0, a3 = 0;
#pragma unroll 10
            for (int k = 0; k < HH; k++) {
                u64 w2 = splat2(WHc[k * H3]);
                ulonglong2 p = *(const ulonglong2*)(hsb + k * ROWS);
                ulonglong2 q = *(const ulonglong2*)(hsb + k * ROWS + 4);
                a0 = fma2(w2, p.x, a0);
                a1 = fma2(w2, p.y, a1);
                a2 = fma2(w2, q.x, a2);
                a3 = fma2(w2, q.y, a3);
            }
            float f0, f1;
            unpk(a0, f0, f1); sm[OFF_GH + 0 * H3 + c] = f0; sm[OFF_GH + 1 * H3 + c] = f1;
            unpk(a1, f0, f1); sm[OFF_GH + 2 * H3 + c] = f0; sm[OFF_GH + 3 * H3 + c] = f1;
            unpk(a2, f0, f1); sm[OFF_GH + 4 * H3 + c] = f0; sm[OFF_GH + 5 * H3 + c] = f1;
            unpk(a3, f0, f1); sm[OFF_GH + 6 * H3 + c] = f0; sm[OFF_GH + 7 * H3 + c] = f1;
        }

        // stash prefetched x tile
        if (pf) {
            float* xd = sm + OFF_XS + nbuf * (VV * ROWS);
            xd[pv * ROWS + pr]       = px.x;
            xd[(pv + 1) * ROWS + pr] = px.y;
        }
        __syncthreads();

        // ---- gate phase: 800 outputs (r, j) ----
        for (int o = tid; o < ROWS * HH; o += RTHREADS) {
            int r = o / 100;
            int j = o - r * 100;
            const float* gx = sm + OFF_GX + r * H3;
            const float* gh = sm + OFF_GH + r * H3;
            float g_r = gx[j]       + gh[j]       + sm[OFF_BRZ + j];
            float g_z = gx[j + 100] + gh[j + 100] + sm[OFF_BRZ + j + 100];
            float i_n = gx[j + 200] + sm[OFF_BIN + j];
            float h_n = gh[j + 200] + sm[OFF_BHN + j];
            float rg = sigmoid_f(g_r);
            float zg = sigmoid_f(g_z);
            float nv = tanhf(fmaf(rg, h_n, i_n));
            float hold = sm[OFF_H2 + r * HH + j];
            float hnew = fmaf(zg, hold - nv, nv);   // (1-z)n + z h
            float hout = (t < len_s[r]) ? hnew : hold;
            sm[OFF_HS + j * ROWS + r] = hout;
            sm[OFF_H2 + r * HH + j]   = hout;
            g_hidden[((size_t)t * BB + row0 + r) * HH + j] = hout;
        }
        __syncthreads();
    }
}

// ---- epilogue: logits + log_softmax + mask, 2 rows per warp ----
__global__ void __launch_bounds__(256)
gru_output_kernel(const int*   __restrict__ lengths,
                  const float* __restrict__ W_out,
                  const float* __restrict__ b_out,
                  float*       __restrict__ out) {
    __shared__ float Wo[HH * VV];    // Wo[k*64 + c]
    __shared__ float bo[VV];
    __shared__ float hrow[8][2][HH];
    const int tid = threadIdx.x;
    for (int e = tid; e < VV * HH; e += 256) {
        int cc = e / 100, k = e - cc * 100;
        Wo[k * VV + cc] = W_out[e];
    }
    if (tid < VV) bo[tid] = b_out[tid];
    __syncthreads();

    const int w = tid >> 5;
    const int lane = tid & 31;
    const int npair = (TT * BB) / 2;
    const float bo0 = bo[lane];
    const float bo1 = bo[lane + 32];

    for (int p = blockIdx.x * 8 + w; p < npair; p += gridDim.x * 8) {
        int rid0 = p * 2;
        int t  = rid0 >> 10;
        int b0 = rid0 & 1023;
        int L0 = lengths[b0];
        int L1 = lengths[b0 + 1];
        bool act0 = t < L0, act1 = t < L1;
        float* op0 = out + (size_t)rid0 * VV;
        float* op1 = op0 + VV;
        if (!act0 && !act1) {
            op0[lane] = 0.0f; op0[lane + 32] = 0.0f;
            op1[lane] = 0.0f; op1[lane + 32] = 0.0f;
            continue;
        }
        const float* hp0 = g_hidden + (size_t)rid0 * HH;
        const float* hp1 = hp0 + HH;
        hrow[w][0][lane]      = hp0[lane];
        hrow[w][0][lane + 32] = hp0[lane + 32];
        hrow[w][0][lane + 64] = hp0[lane + 64];
        hrow[w][1][lane]      = hp1[lane];
        hrow[w][1][lane + 32] = hp1[lane + 32];
        hrow[w][1][lane + 64] = hp1[lane + 64];
        if (lane < 4) {
            hrow[w][0][lane + 96] = hp0[lane + 96];
            hrow[w][1][lane + 96] = hp1[lane + 96];
        }
        __syncwarp();
        float a00 = 0.0f, a01 = 0.0f, a10 = 0.0f, a11 = 0.0f;
#pragma unroll 5
        for (int k = 0; k < HH; k++) {
            float w0 = Wo[k * VV + lane];
            float w1 = Wo[k * VV + lane + 32];
            float h0v = hrow[w][0][k];
            float h1v = hrow[w][1][k];
            a00 = fmaf(h0v, w0, a00);
            a01 = fmaf(h0v, w1, a01);
            a10 = fmaf(h1v, w0, a10);
            a11 = fmaf(h1v, w1, a11);
        }
        // row 0
        {
            float l0 = a00 + bo0, l1 = a01 + bo1;
            float m = fmaxf(l0, l1);
#pragma unroll
            for (int s = 16; s; s >>= 1) m = fmaxf(m, __shfl_xor_sync(0xffffffffu, m, s));
            float se = __expf(l0 - m) + __expf(l1 - m);
#pragma unroll
            for (int s = 16; s; s >>= 1) se += __shfl_xor_sync(0xffffffffu, se, s);
            float lse = m + __logf(se);
            op0[lane]      = act0 ? (l0 - lse) : 0.0f;
            op0[lane + 32] = act0 ? (l1 - lse) : 0.0f;
        }
        // row 1
        {
            float l0 = a10 + bo0, l1 = a11 + bo1;
            float m = fmaxf(l0, l1);
#pragma unroll
            for (int s = 16; s; s >>= 1) m = fmaxf(m, __shfl_xor_sync(0xffffffffu, m, s));
            float se = __expf(l0 - m) + __expf(l1 - m);
#pragma unroll
            for (int s = 16; s; s >>= 1) se += __shfl_xor_sync(0xffffffffu, se, s);
            float lse = m + __logf(se);
            op1[lane]      = act1 ? (l0 - lse) : 0.0f;
            op1[lane + 32] = act1 ? (l1 - lse) : 0.0f;
        }
        __syncwarp();
    }
}

extern "C" void kernel_launch(void* const* d_in, const int* in_sizes, int n_in,
                              void* d_out, int out_size) {
    const float* x      = (const float*)d_in[0];
    const float* h0     = (const float*)d_in[1];
    const int*   lens   = (const int*)  d_in[2];
    const float* W_ih   = (const float*)d_in[3];
    const float* W_hh   = (const float*)d_in[4];
    const float* b_ih   = (const float*)d_in[5];
    const float* b_hh   = (const float*)d_in[6];
    const float* W_out  = (const float*)d_in[7];
    const float* b_out  = (const float*)d_in[8];
    float* out = (float*)d_out;

    cudaFuncSetAttribute(gru_recurrent_kernel,
                         cudaFuncAttributeMaxDynamicSharedMemorySize, SMEM_BYTES);

    gru_recurrent_kernel<<<NBLK, RTHREADS, SMEM_BYTES>>>(
        x, h0, lens, W_ih, W_hh, b_ih, b_hh);
    gru_output_kernel<<<2048, 256>>>(lens, W_out, b_out, out);
}

// round 3
// speedup vs baseline: 1.3831x; 1.2093x over previous
#include <cuda_runtime.h>
#include <cstdint>

#define TT 512
#define BB 1024
#define VV 64
#define HH 100
#define H3 300
#define ROWS 8
#define NBLK 128
#define RT 640
#define PT 640

// device scratch
__device__ float g_hidden[(size_t)TT * BB * HH];   // [t][b][j]  210 MB
__device__ float g_gi[(size_t)TT * BB * H3];       // [t][b][c]  630 MB (biases folded)

typedef unsigned long long u64;

__device__ __forceinline__ u64 splat2(float w) {
    u64 r; asm("mov.b64 %0, {%1, %1};" : "=l"(r) : "f"(w)); return r;
}
__device__ __forceinline__ u64 fma2(u64 a, u64 b, u64 c) {
    u64 d; asm("fma.rn.f32x2 %0, %1, %2, %3;" : "=l"(d) : "l"(a), "l"(b), "l"(c)); return d;
}
__device__ __forceinline__ void unpk(u64 v, float& lo, float& hi) {
    asm("mov.b64 {%0, %1}, %2;" : "=f"(lo), "=f"(hi) : "l"(v));
}
__device__ __forceinline__ float sigmoid_f(float x) {
    return 1.0f / (1.0f + __expf(-x));
}

// ============================================================
// Pre-kernel: gi[t][b][c] = x[t][b][:] @ W_ih[c][:] + b_ih[c] (+ b_hh[c] for c<200)
// grid = TT blocks (one t each), PT threads.
// thread = (rq = tid/80 in [0,8), cq = tid%80 < 75), 4 cols each, 8 rows each,
// 16 passes of 64 rows.
// ============================================================
#define PRE_SMEM_FLOATS (19200 + 64 * 68 + 300 + 4)
__global__ void __launch_bounds__(PT)
gi_precompute_kernel(const float* __restrict__ x,
                     const float* __restrict__ W_ih,
                     const float* __restrict__ b_ih,
                     const float* __restrict__ b_hh) {
    extern __shared__ float sm[];
    float* Wih_s = sm;                 // [64][300]  Wih_s[v*300+c]
    float* xs    = sm + 19200;         // [64][68]   xs[v*68 + row]
    float* bs    = sm + 19200 + 64 * 68;

    const int tid = threadIdx.x;
    const int t = blockIdx.x;

    for (int e = tid; e < H3 * VV; e += PT) {
        int c = e >> 6, v = e & 63;
        Wih_s[v * H3 + c] = W_ih[e];
    }
    for (int c = tid; c < H3; c += PT)
        bs[c] = b_ih[c] + ((c < 200) ? b_hh[c] : 0.0f);

    const int rq = tid / 80;
    const int cq = tid - rq * 80;
    const bool act = (cq < 75);

    for (int pass = 0; pass < 16; pass++) {
        const int b0 = pass * 64;
        __syncthreads();   // protect xs from previous pass readers
        for (int e = tid; e < 64 * 64; e += PT) {
            int row = e >> 6, v = e & 63;
            xs[v * 68 + row] = x[((size_t)t * BB + b0 + row) * VV + v];
        }
        __syncthreads();
        if (act) {
            u64 a0[4], a1[4], a2[4], a3[4];
#pragma unroll
            for (int i = 0; i < 4; i++) { a0[i] = 0; a1[i] = 0; a2[i] = 0; a3[i] = 0; }
            const float* w0p = Wih_s + cq;
            const float* w1p = Wih_s + cq + 75;
            const float* w2p = Wih_s + cq + 150;
            const float* w3p = Wih_s + cq + 225;
            const float* xb  = xs + rq * 8;
#pragma unroll 4
            for (int v = 0; v < VV; v++) {
                u64 w0 = splat2(w0p[v * H3]);
                u64 w1 = splat2(w1p[v * H3]);
                u64 w2 = splat2(w2p[v * H3]);
                u64 w3 = splat2(w3p[v * H3]);
                ulonglong2 p = *(const ulonglong2*)(xb + v * 68);
                ulonglong2 q = *(const ulonglong2*)(xb + v * 68 + 4);
                a0[0] = fma2(w0, p.x, a0[0]); a0[1] = fma2(w0, p.y, a0[1]);
                a0[2] = fma2(w0, q.x, a0[2]); a0[3] = fma2(w0, q.y, a0[3]);
                a1[0] = fma2(w1, p.x, a1[0]); a1[1] = fma2(w1, p.y, a1[1]);
                a1[2] = fma2(w1, q.x, a1[2]); a1[3] = fma2(w1, q.y, a1[3]);
                a2[0] = fma2(w2, p.x, a2[0]); a2[1] = fma2(w2, p.y, a2[1]);
                a2[2] = fma2(w2, q.x, a2[2]); a2[3] = fma2(w2, q.y, a2[3]);
                a3[0] = fma2(w3, p.x, a3[0]); a3[1] = fma2(w3, p.y, a3[1]);
                a3[2] = fma2(w3, q.x, a3[2]); a3[3] = fma2(w3, q.y, a3[3]);
            }
            const int rowbase = b0 + rq * 8;
            u64* accs[4] = {a0, a1, a2, a3};
#pragma unroll
            for (int jj = 0; jj < 4; jj++) {
                int c = cq + jj * 75;
                float bb = bs[c];
                float f[8];
                unpk(accs[jj][0], f[0], f[1]);
                unpk(accs[jj][1], f[2], f[3]);
                unpk(accs[jj][2], f[4], f[5]);
                unpk(accs[jj][3], f[6], f[7]);
#pragma unroll
                for (int rr = 0; rr < 8; rr++)
                    g_gi[((size_t)t * BB + rowbase + rr) * H3 + c] = f[rr] + bb;
            }
        }
    }
}

// ============================================================
// Recurrent kernel: h-part only.
// thread = (kq = tid/160 in [0,4), cp = tid%160 < 150), cols cp, cp+150,
// k range kq*25..kq*25+25. gi streamed via double-buffered cp.async.
// ============================================================
#define OFF_WH 0                  // [100][300] Wh_s[k*300+c]
#define OFF_HS 30000              // [100][8]   hs[j*8+r]
#define OFF_PG 30800              // [4][300][8] pg[kq*2400 + c*8 + r]
#define OFF_GI 40400              // [2][8][300] gi_s[buf*2400 + r*300 + c]
#define OFF_BHN 45200             // [100]
#define OFF_LEN 45300             // 8 ints
#define REC_SMEM_FLOATS (OFF_LEN + 8)
#define REC_SMEM_BYTES (REC_SMEM_FLOATS * 4)

__global__ void __launch_bounds__(RT, 1)
gru_recurrent_kernel(const float* __restrict__ h0,
                     const int*   __restrict__ lengths,
                     const float* __restrict__ W_hh,
                     const float* __restrict__ b_hh) {
    extern __shared__ float sm[];
    int* len_s = (int*)(sm + OFF_LEN);
    const int tid = threadIdx.x;
    const int row0 = blockIdx.x * ROWS;

    // Wh transposed: global [300][100] -> Wh_s[k*300+c]
    for (int e = tid; e < H3 * HH; e += RT) {
        int c = e / 100, k = e - c * 100;
        sm[OFF_WH + k * H3 + c] = W_hh[e];
    }
    if (tid < 100) sm[OFF_BHN + tid] = b_hh[200 + tid];
    for (int e = tid; e < ROWS * HH; e += RT) {
        int r = e & 7, j = e >> 3;
        sm[OFF_HS + j * ROWS + r] = h0[(size_t)(row0 + r) * HH + j];
    }
    if (tid < ROWS) len_s[tid] = lengths[row0 + tid];

    // prefetch gi tile for t=0 into buf 0
    if (tid < 600) {
        unsigned int sa = (unsigned int)__cvta_generic_to_shared(sm + OFF_GI + tid * 4);
        const float* gp = g_gi + ((size_t)0 * BB + row0) * H3 + tid * 4;
        asm volatile("cp.async.ca.shared.global [%0], [%1], 16;" :: "r"(sa), "l"(gp));
    }
    asm volatile("cp.async.commit_group;");
    __syncthreads();

    int ml = len_s[0];
#pragma unroll
    for (int i = 1; i < ROWS; i++) ml = max(ml, len_s[i]);

    const int kq = tid / 160;
    const int cp = tid - kq * 160;
    const bool act = (cp < 150);
    const int kbase = kq * 25;

    for (int t = 0; t < ml; t++) {
        const int buf = t & 1;
        const int nbuf = buf ^ 1;
        // prefetch gi for t+1 (clamped; duplicate read discarded on last iter)
        {
            int tp = (t + 1 < ml) ? (t + 1) : t;
            if (tid < 600) {
                unsigned int sa = (unsigned int)__cvta_generic_to_shared(
                    sm + OFF_GI + nbuf * 2400 + tid * 4);
                const float* gp = g_gi + ((size_t)tp * BB + row0) * H3 + tid * 4;
                asm volatile("cp.async.ca.shared.global [%0], [%1], 16;" :: "r"(sa), "l"(gp));
            }
            asm volatile("cp.async.commit_group;");
        }

        if (act) {
            const float* w0p = sm + OFF_WH + cp;
            const float* w1p = sm + OFF_WH + cp + 150;
            const float* hsb = sm + OFF_HS;
            u64 a0[4], a1[4];
#pragma unroll
            for (int i = 0; i < 4; i++) { a0[i] = 0; a1[i] = 0; }
#pragma unroll 5
            for (int i = 0; i < 25; i++) {
                int k = kbase + i;
                u64 w0 = splat2(w0p[k * H3]);
                u64 w1 = splat2(w1p[k * H3]);
                ulonglong2 p = *(const ulonglong2*)(hsb + k * ROWS);
                ulonglong2 q = *(const ulonglong2*)(hsb + k * ROWS + 4);
                a0[0] = fma2(w0, p.x, a0[0]); a0[1] = fma2(w0, p.y, a0[1]);
                a0[2] = fma2(w0, q.x, a0[2]); a0[3] = fma2(w0, q.y, a0[3]);
                a1[0] = fma2(w1, p.x, a1[0]); a1[1] = fma2(w1, p.y, a1[1]);
                a1[2] = fma2(w1, q.x, a1[2]); a1[3] = fma2(w1, q.y, a1[3]);
            }
            float* pg0 = sm + OFF_PG + kq * 2400 + cp * ROWS;
            *(ulonglong2*)(pg0)           = make_ulonglong2(a0[0], a0[1]);
            *(ulonglong2*)(pg0 + 4)       = make_ulonglong2(a0[2], a0[3]);
            *(ulonglong2*)(pg0 + 150 * 8)     = make_ulonglong2(a1[0], a1[1]);
            *(ulonglong2*)(pg0 + 150 * 8 + 4) = make_ulonglong2(a1[2], a1[3]);
        }
        asm volatile("cp.async.wait_group 1;");
        __syncthreads();

        // ---- gate phase: 800 outputs, o -> (r = o&7, j = o>>3) ----
        for (int o = tid; o < ROWS * HH; o += RT) {
            int r = o & 7;
            int j = o >> 3;
            const float* pg = sm + OFF_PG;
            int br = j * ROWS + r;
            int bz = (j + 100) * ROWS + r;
            int bn = (j + 200) * ROWS + r;
            float s_r = pg[br] + pg[br + 2400] + pg[br + 4800] + pg[br + 7200];
            float s_z = pg[bz] + pg[bz + 2400] + pg[bz + 4800] + pg[bz + 7200];
            float s_n = pg[bn] + pg[bn + 2400] + pg[bn + 4800] + pg[bn + 7200];
            const float* gs = sm + OFF_GI + buf * 2400 + r * H3 + j;
            float rg = sigmoid_f(gs[0] + s_r);
            float zg = sigmoid_f(gs[100] + s_z);
            float hn = s_n + sm[OFF_BHN + j];
            float nv = tanhf(fmaf(rg, hn, gs[200]));
            float hold = sm[OFF_HS + j * ROWS + r];
            float hnew = fmaf(zg, hold - nv, nv);
            float hout = (t < len_s[r]) ? hnew : hold;
            sm[OFF_HS + j * ROWS + r] = hout;
            g_hidden[((size_t)t * BB + row0 + r) * HH + j] = hout;
        }
        __syncthreads();
    }
}

// ============================================================
// Epilogue: logits + log_softmax + mask, 4 rows per warp.
// ============================================================
__global__ void __launch_bounds__(256)
gru_output_kernel(const int*   __restrict__ lengths,
                  const float* __restrict__ W_out,
                  const float* __restrict__ b_out,
                  float*       __restrict__ out) {
    __shared__ float Wo[HH * VV];      // Wo[k*64 + c]
    __shared__ float bo[VV];
    __shared__ float hq[8][HH * 4];    // hq[w][k*4 + i]
    const int tid = threadIdx.x;
    for (int e = tid; e < VV * HH; e += 256) {
        int cc = e / 100, k = e - cc * 100;
        Wo[k * VV + cc] = W_out[e];
    }
    if (tid < VV) bo[tid] = b_out[tid];
    __syncthreads();

    const int w = tid >> 5;
    const int lane = tid & 31;
    const float bo0 = bo[lane];
    const float bo1 = bo[lane + 32];
    const int nquad = (TT * BB) / 4;

    for (int q = blockIdx.x * 8 + w; q < nquad; q += gridDim.x * 8) {
        int rid0 = q * 4;
        int t  = rid0 >> 10;
        int b0 = rid0 & 1023;
        int L0 = lengths[b0];
        float* op = out + (size_t)rid0 * VV;
        if (t >= L0) {   // lengths sorted desc -> all 4 rows inactive
#pragma unroll
            for (int i = 0; i < 4; i++) {
                op[i * VV + lane] = 0.0f;
                op[i * VV + lane + 32] = 0.0f;
            }
            continue;
        }
        int L1 = lengths[b0 + 1], L2 = lengths[b0 + 2], L3 = lengths[b0 + 3];
        bool act[4] = {true, t < L1, t < L2, t < L3};

#pragma unroll
        for (int i = 0; i < 4; i++) {
            const float* hp = g_hidden + (size_t)(rid0 + i) * HH;
            hq[w][lane * 4 + i]        = hp[lane];
            hq[w][(lane + 32) * 4 + i] = hp[lane + 32];
            hq[w][(lane + 64) * 4 + i] = hp[lane + 64];
            if (lane < 4) hq[w][(lane + 96) * 4 + i] = hp[lane + 96];
        }
        __syncwarp();
        float acc0[4] = {0.f, 0.f, 0.f, 0.f};
        float acc1[4] = {0.f, 0.f, 0.f, 0.f};
#pragma unroll 5
        for (int k = 0; k < HH; k++) {
            float4 hv = *(const float4*)&hq[w][k * 4];
            float w0 = Wo[k * VV + lane];
            float w1 = Wo[k * VV + lane + 32];
            acc0[0] = fmaf(hv.x, w0, acc0[0]); acc1[0] = fmaf(hv.x, w1, acc1[0]);
            acc0[1] = fmaf(hv.y, w0, acc0[1]); acc1[1] = fmaf(hv.y, w1, acc1[1]);
            acc0[2] = fmaf(hv.z, w0, acc0[2]); acc1[2] = fmaf(hv.z, w1, acc1[2]);
            acc0[3] = fmaf(hv.w, w0, acc0[3]); acc1[3] = fmaf(hv.w, w1, acc1[3]);
        }
#pragma unroll
        for (int i = 0; i < 4; i++) {
            float l0 = acc0[i] + bo0;
            float l1 = acc1[i] + bo1;
            float m = fmaxf(l0, l1);
#pragma unroll
            for (int s = 16; s; s >>= 1) m = fmaxf(m, __shfl_xor_sync(0xffffffffu, m, s));
            float se = __expf(l0 - m) + __expf(l1 - m);
#pragma unroll
            for (int s = 16; s; s >>= 1) se += __shfl_xor_sync(0xffffffffu, se, s);
            float lse = m + __logf(se);
            op[i * VV + lane]      = act[i] ? (l0 - lse) : 0.0f;
            op[i * VV + lane + 32] = act[i] ? (l1 - lse) : 0.0f;
        }
        __syncwarp();
    }
}

extern "C" void kernel_launch(void* const* d_in, const int* in_sizes, int n_in,
                              void* d_out, int out_size) {
    const float* x      = (const float*)d_in[0];
    const float* h0     = (const float*)d_in[1];
    const int*   lens   = (const int*)  d_in[2];
    const float* W_ih   = (const float*)d_in[3];
    const float* W_hh   = (const float*)d_in[4];
    const float* b_ih   = (const float*)d_in[5];
    const float* b_hh   = (const float*)d_in[6];
    const float* W_out  = (const float*)d_in[7];
    const float* b_out  = (const float*)d_in[8];
    float* out = (float*)d_out;

    static int configured = 0;
    cudaFuncSetAttribute(gi_precompute_kernel,
                         cudaFuncAttributeMaxDynamicSharedMemorySize, PRE_SMEM_FLOATS * 4);
    cudaFuncSetAttribute(gru_recurrent_kernel,
                         cudaFuncAttributeMaxDynamicSharedMemorySize, REC_SMEM_BYTES);
    (void)configured;

    gi_precompute_kernel<<<TT, PT, PRE_SMEM_FLOATS * 4>>>(x, W_ih, b_ih, b_hh);
    gru_recurrent_kernel<<<NBLK, RT, REC_SMEM_BYTES>>>(h0, lens, W_hh, b_hh);
    gru_output_kernel<<<2048, 256>>>(lens, W_out, b_out, out);
}

// round 4
// speedup vs baseline: 1.8286x; 1.3221x over previous
#include <cuda_runtime.h>
#include <cstdint>

#define TT 512
#define BB 1024
#define VV 64
#define HH 100
#define H3 300
#define ROWS 8
#define NBLK 128
#define RT 640
#define PT 320

// device scratch
__device__ float g_hidden[(size_t)TT * BB * HH];   // [t][b][j]  210 MB
__device__ float g_gi[(size_t)TT * BB * H3];       // [t][b][c]  630 MB (biases folded)

typedef unsigned long long u64;

__device__ __forceinline__ u64 splat2(float w) {
    u64 r; asm("mov.b64 %0, {%1, %1};" : "=l"(r) : "f"(w)); return r;
}
__device__ __forceinline__ u64 fma2(u64 a, u64 b, u64 c) {
    u64 d; asm("fma.rn.f32x2 %0, %1, %2, %3;" : "=l"(d) : "l"(a), "l"(b), "l"(c)); return d;
}
__device__ __forceinline__ void unpk(u64 v, float& lo, float& hi) {
    asm("mov.b64 {%0, %1}, %2;" : "=f"(lo), "=f"(hi) : "l"(v));
}
__device__ __forceinline__ float sigmoid_f(float x) {
    return 1.0f / (1.0f + __expf(-x));
}

// ============================================================
// Pre-kernel: gi[t][b][c] = x[t][b][:] @ W_ih[c][:] + b_ih[c] (+ b_hh[c] for c<200)
// grid = 1024: (t = bid>>1, half-batch = bid&1). 320 threads, 2 CTAs/SM.
// thread = (rq = tid/80 in [0,4), cq = tid%80 < 75): 8 rows x 4 cols,
// 16 passes of 32 rows, x tile double-buffered via register prefetch.
// ============================================================
#define PRE_XS_STRIDE 36
#define PRE_XS_FLOATS (64 * PRE_XS_STRIDE)         // 2304
#define PRE_SMEM_FLOATS (19200 + 304 + 2 * PRE_XS_FLOATS)
__global__ void __launch_bounds__(PT, 2)
gi_precompute_kernel(const float* __restrict__ x,
                     const float* __restrict__ W_ih,
                     const float* __restrict__ b_ih,
                     const float* __restrict__ b_hh) {
    extern __shared__ float sm[];
    float* Wih_s = sm;                     // [64][300]  Wih_s[v*300+c]
    float* bs    = sm + 19200;             // [300]+pad
    float* xs    = sm + 19504;             // [2][64][36] xs[buf][v*36+row]

    const int tid = threadIdx.x;
    const int t = blockIdx.x >> 1;
    const int rbase = (blockIdx.x & 1) * 512;

    for (int e = tid; e < H3 * VV; e += PT) {
        int c = e >> 6, v = e & 63;
        Wih_s[v * H3 + c] = W_ih[e];
    }
    for (int c = tid; c < H3; c += PT)
        bs[c] = b_ih[c] + ((c < 200) ? b_hh[c] : 0.0f);

    const size_t xrow0 = (size_t)t * BB + rbase;
    // pass 0 x tile
    for (int e = tid; e < 2048; e += PT) {
        int row = e >> 6, v = e & 63;
        xs[v * PRE_XS_STRIDE + row] = x[(xrow0 + row) * VV + v];
    }
    __syncthreads();

    const int rq = tid / 80;
    const int cq = tid - rq * 80;
    const bool act = (cq < 75);

    for (int pass = 0; pass < 16; pass++) {
        const int buf = pass & 1;
        const bool has = (pass + 1 < 16);
        float pf[7];
        if (has) {
            const size_t base = (xrow0 + (pass + 1) * 32) * VV;
#pragma unroll
            for (int i = 0; i < 7; i++) {
                int e = tid + i * PT;
                if (e < 2048) {
                    int row = e >> 6, v = e & 63;
                    pf[i] = x[base + (size_t)row * VV + v];
                }
            }
        }
        if (act) {
            u64 a0[4], a1[4], a2[4], a3[4];
#pragma unroll
            for (int i = 0; i < 4; i++) { a0[i] = 0; a1[i] = 0; a2[i] = 0; a3[i] = 0; }
            const float* w0p = Wih_s + cq;
            const float* w1p = Wih_s + cq + 75;
            const float* w2p = Wih_s + cq + 150;
            const float* w3p = Wih_s + cq + 225;
            const float* xb  = xs + buf * PRE_XS_FLOATS + rq * 8;
#pragma unroll 4
            for (int v = 0; v < VV; v++) {
                u64 w0 = splat2(w0p[v * H3]);
                u64 w1 = splat2(w1p[v * H3]);
                u64 w2 = splat2(w2p[v * H3]);
                u64 w3 = splat2(w3p[v * H3]);
                ulonglong2 p = *(const ulonglong2*)(xb + v * PRE_XS_STRIDE);
                ulonglong2 q = *(const ulonglong2*)(xb + v * PRE_XS_STRIDE + 4);
                a0[0] = fma2(w0, p.x, a0[0]); a0[1] = fma2(w0, p.y, a0[1]);
                a0[2] = fma2(w0, q.x, a0[2]); a0[3] = fma2(w0, q.y, a0[3]);
                a1[0] = fma2(w1, p.x, a1[0]); a1[1] = fma2(w1, p.y, a1[1]);
                a1[2] = fma2(w1, q.x, a1[2]); a1[3] = fma2(w1, q.y, a1[3]);
                a2[0] = fma2(w2, p.x, a2[0]); a2[1] = fma2(w2, p.y, a2[1]);
                a2[2] = fma2(w2, q.x, a2[2]); a2[3] = fma2(w2, q.y, a2[3]);
                a3[0] = fma2(w3, p.x, a3[0]); a3[1] = fma2(w3, p.y, a3[1]);
                a3[2] = fma2(w3, q.x, a3[2]); a3[3] = fma2(w3, q.y, a3[3]);
            }
            const size_t rowbase = xrow0 + pass * 32 + rq * 8;
            u64* accs[4] = {a0, a1, a2, a3};
#pragma unroll
            for (int jj = 0; jj < 4; jj++) {
                int c = cq + jj * 75;
                float bb = bs[c];
                float f[8];
                unpk(accs[jj][0], f[0], f[1]);
                unpk(accs[jj][1], f[2], f[3]);
                unpk(accs[jj][2], f[4], f[5]);
                unpk(accs[jj][3], f[6], f[7]);
#pragma unroll
                for (int rr = 0; rr < 8; rr++)
                    g_gi[(rowbase + rr) * H3 + c] = f[rr] + bb;
            }
        }
        if (has) {
            float* xd = xs + (buf ^ 1) * PRE_XS_FLOATS;
#pragma unroll
            for (int i = 0; i < 7; i++) {
                int e = tid + i * PT;
                if (e < 2048) {
                    int row = e >> 6, v = e & 63;
                    xd[v * PRE_XS_STRIDE + row] = pf[i];
                }
            }
        }
        __syncthreads();
    }
}

// ============================================================
// Recurrent kernel: h-part only, W_hh held in REGISTERS.
// thread = (kq = tid/160 in [0,4), cp = tid%160 < 150), cols cp, cp+150,
// k range kq*25..+25. gi streamed via double-buffered cp.async.
// ============================================================
#define OFF_HS 0                  // [100][8]   hs[j*8+r]
#define OFF_PG 800                // [4][300][8] pg[kq*2400 + c*8 + r]
#define OFF_GI 10400              // [2][8][300] gi_s[buf*2400 + r*300 + c]
#define OFF_BHN 15200             // [100]
#define OFF_LEN 15300             // 8 ints
#define REC_SMEM_FLOATS (OFF_LEN + 8)
#define REC_SMEM_BYTES (REC_SMEM_FLOATS * 4)

__global__ void __launch_bounds__(RT, 1)
gru_recurrent_kernel(const float* __restrict__ h0,
                     const int*   __restrict__ lengths,
                     const float* __restrict__ W_hh,
                     const float* __restrict__ b_hh) {
    extern __shared__ float sm[];
    int* len_s = (int*)(sm + OFF_LEN);
    const int tid = threadIdx.x;
    const int row0 = blockIdx.x * ROWS;

    if (tid < 100) sm[OFF_BHN + tid] = b_hh[200 + tid];
    for (int e = tid; e < ROWS * HH; e += RT) {
        int r = e & 7, j = e >> 3;
        sm[OFF_HS + j * ROWS + r] = h0[(size_t)(row0 + r) * HH + j];
    }
    if (tid < ROWS) len_s[tid] = lengths[row0 + tid];

    const int kq = tid / 160;
    const int cp = tid - kq * 160;
    const bool act = (cp < 150);
    const int kbase = kq * 25;

    // weights -> registers: W_hh is [300][100], w(c,k) = W_hh[c*100+k],
    // 25 consecutive per (thread, col).
    float wA[25], wB[25];
    if (act) {
        const float* pA = W_hh + cp * 100 + kbase;
        const float* pB = W_hh + (cp + 150) * 100 + kbase;
#pragma unroll
        for (int i = 0; i < 25; i++) { wA[i] = pA[i]; wB[i] = pB[i]; }
    }

    // prefetch gi tile for t=0 into buf 0
    if (tid < 600) {
        unsigned int sa = (unsigned int)__cvta_generic_to_shared(sm + OFF_GI + tid * 4);
        const float* gp = g_gi + ((size_t)0 * BB + row0) * H3 + tid * 4;
        asm volatile("cp.async.ca.shared.global [%0], [%1], 16;" :: "r"(sa), "l"(gp));
    }
    asm volatile("cp.async.commit_group;");
    __syncthreads();

    int ml = len_s[0];
#pragma unroll
    for (int i = 1; i < ROWS; i++) ml = max(ml, len_s[i]);

    for (int t = 0; t < ml; t++) {
        const int buf = t & 1;
        const int nbuf = buf ^ 1;
        {
            int tp = (t + 1 < ml) ? (t + 1) : t;
            if (tid < 600) {
                unsigned int sa = (unsigned int)__cvta_generic_to_shared(
                    sm + OFF_GI + nbuf * 2400 + tid * 4);
                const float* gp = g_gi + ((size_t)tp * BB + row0) * H3 + tid * 4;
                asm volatile("cp.async.ca.shared.global [%0], [%1], 16;" :: "r"(sa), "l"(gp));
            }
            asm volatile("cp.async.commit_group;");
        }

        if (act) {
            const float* hsb = sm + OFF_HS + kbase * ROWS;
            u64 a0[4], a1[4];
#pragma unroll
            for (int i = 0; i < 4; i++) { a0[i] = 0; a1[i] = 0; }
#pragma unroll
            for (int i = 0; i < 25; i++) {
                u64 w0 = splat2(wA[i]);
                u64 w1 = splat2(wB[i]);
                ulonglong2 p = *(const ulonglong2*)(hsb + i * ROWS);
                ulonglong2 q = *(const ulonglong2*)(hsb + i * ROWS + 4);
                a0[0] = fma2(w0, p.x, a0[0]); a0[1] = fma2(w0, p.y, a0[1]);
                a0[2] = fma2(w0, q.x, a0[2]); a0[3] = fma2(w0, q.y, a0[3]);
                a1[0] = fma2(w1, p.x, a1[0]); a1[1] = fma2(w1, p.y, a1[1]);
                a1[2] = fma2(w1, q.x, a1[2]); a1[3] = fma2(w1, q.y, a1[3]);
            }
            float* pg0 = sm + OFF_PG + kq * 2400 + cp * ROWS;
            *(ulonglong2*)(pg0)               = make_ulonglong2(a0[0], a0[1]);
            *(ulonglong2*)(pg0 + 4)           = make_ulonglong2(a0[2], a0[3]);
            *(ulonglong2*)(pg0 + 150 * 8)     = make_ulonglong2(a1[0], a1[1]);
            *(ulonglong2*)(pg0 + 150 * 8 + 4) = make_ulonglong2(a1[2], a1[3]);
        }
        asm volatile("cp.async.wait_group 1;");
        __syncthreads();

        // ---- gate phase: 800 outputs, o -> (r = o&7, j = o>>3) ----
        for (int o = tid; o < ROWS * HH; o += RT) {
            int r = o & 7;
            int j = o >> 3;
            const float* pg = sm + OFF_PG;
            int br = j * ROWS + r;
            int bz = (j + 100) * ROWS + r;
            int bn = (j + 200) * ROWS + r;
            float s_r = pg[br] + pg[br + 2400] + pg[br + 4800] + pg[br + 7200];
            float s_z = pg[bz] + pg[bz + 2400] + pg[bz + 4800] + pg[bz + 7200];
            float s_n = pg[bn] + pg[bn + 2400] + pg[bn + 4800] + pg[bn + 7200];
            const float* gs = sm + OFF_GI + buf * 2400 + r * H3 + j;
            float rg = sigmoid_f(gs[0] + s_r);
            float zg = sigmoid_f(gs[100] + s_z);
            float hn = s_n + sm[OFF_BHN + j];
            float nv = tanhf(fmaf(rg, hn, gs[200]));
            float hold = sm[OFF_HS + j * ROWS + r];
            float hnew = fmaf(zg, hold - nv, nv);
            float hout = (t < len_s[r]) ? hnew : hold;
            sm[OFF_HS + j * ROWS + r] = hout;
            g_hidden[((size_t)t * BB + row0 + r) * HH + j] = hout;
        }
        __syncthreads();
    }
}

// ============================================================
// Epilogue: logits + log_softmax + mask, 4 rows per warp.
// ============================================================
__global__ void __launch_bounds__(256)
gru_output_kernel(const int*   __restrict__ lengths,
                  const float* __restrict__ W_out,
                  const float* __restrict__ b_out,
                  float*       __restrict__ out) {
    __shared__ float Wo[HH * VV];      // Wo[k*64 + c]
    __shared__ float bo[VV];
    __shared__ float hq[8][HH * 4];    // hq[w][k*4 + i]
    const int tid = threadIdx.x;
    for (int e = tid; e < VV * HH; e += 256) {
        int cc = e / 100, k = e - cc * 100;
        Wo[k * VV + cc] = W_out[e];
    }
    if (tid < VV) bo[tid] = b_out[tid];
    __syncthreads();

    const int w = tid >> 5;
    const int lane = tid & 31;
    const float bo0 = bo[lane];
    const float bo1 = bo[lane + 32];
    const int nquad = (TT * BB) / 4;

    for (int q = blockIdx.x * 8 + w; q < nquad; q += gridDim.x * 8) {
        int rid0 = q * 4;
        int t  = rid0 >> 10;
        int b0 = rid0 & 1023;
        int L0 = lengths[b0];
        float* op = out + (size_t)rid0 * VV;
        if (t >= L0) {   // lengths sorted desc -> all 4 rows inactive
#pragma unroll
            for (int i = 0; i < 4; i++) {
                op[i * VV + lane] = 0.0f;
                op[i * VV + lane + 32] = 0.0f;
            }
            continue;
        }
        int L1 = lengths[b0 + 1], L2 = lengths[b0 + 2], L3 = lengths[b0 + 3];
        bool act[4] = {true, t < L1, t < L2, t < L3};

#pragma unroll
        for (int i = 0; i < 4; i++) {
            const float* hp = g_hidden + (size_t)(rid0 + i) * HH;
            hq[w][lane * 4 + i]        = hp[lane];
            hq[w][(lane + 32) * 4 + i] = hp[lane + 32];
            hq[w][(lane + 64) * 4 + i] = hp[lane + 64];
            if (lane < 4) hq[w][(lane + 96) * 4 + i] = hp[lane + 96];
        }
        __syncwarp();
        float acc0[4] = {0.f, 0.f, 0.f, 0.f};
        float acc1[4] = {0.f, 0.f, 0.f, 0.f};
#pragma unroll 5
        for (int k = 0; k < HH; k++) {
            float4 hv = *(const float4*)&hq[w][k * 4];
            float w0 = Wo[k * VV + lane];
            float w1 = Wo[k * VV + lane + 32];
            acc0[0] = fmaf(hv.x, w0, acc0[0]); acc1[0] = fmaf(hv.x, w1, acc1[0]);
            acc0[1] = fmaf(hv.y, w0, acc0[1]); acc1[1] = fmaf(hv.y, w1, acc1[1]);
            acc0[2] = fmaf(hv.z, w0, acc0[2]); acc1[2] = fmaf(hv.z, w1, acc1[2]);
            acc0[3] = fmaf(hv.w, w0, acc0[3]); acc1[3] = fmaf(hv.w, w1, acc1[3]);
        }
#pragma unroll
        for (int i = 0; i < 4; i++) {
            float l0 = acc0[i] + bo0;
            float l1 = acc1[i] + bo1;
            float m = fmaxf(l0, l1);
#pragma unroll
            for (int s = 16; s; s >>= 1) m = fmaxf(m, __shfl_xor_sync(0xffffffffu, m, s));
            float se = __expf(l0 - m) + __expf(l1 - m);
#pragma unroll
            for (int s = 16; s; s >>= 1) se += __shfl_xor_sync(0xffffffffu, se, s);
            float lse = m + __logf(se);
            op[i * VV + lane]      = act[i] ? (l0 - lse) : 0.0f;
            op[i * VV + lane + 32] = act[i] ? (l1 - lse) : 0.0f;
        }
        __syncwarp();
    }
}

extern "C" void kernel_launch(void* const* d_in, const int* in_sizes, int n_in,
                              void* d_out, int out_size) {
    const float* x      = (const float*)d_in[0];
    const float* h0     = (const float*)d_in[1];
    const int*   lens   = (const int*)  d_in[2];
    const float* W_ih   = (const float*)d_in[3];
    const float* W_hh   = (const float*)d_in[4];
    const float* b_ih   = (const float*)d_in[5];
    const float* b_hh   = (const float*)d_in[6];
    const float* W_out  = (const float*)d_in[7];
    const float* b_out  = (const float*)d_in[8];
    float* out = (float*)d_out;

    cudaFuncSetAttribute(gi_precompute_kernel,
                         cudaFuncAttributeMaxDynamicSharedMemorySize, PRE_SMEM_FLOATS * 4);
    cudaFuncSetAttribute(gru_recurrent_kernel,
                         cudaFuncAttributeMaxDynamicSharedMemorySize, REC_SMEM_BYTES);

    gi_precompute_kernel<<<2 * TT, PT, PRE_SMEM_FLOATS * 4>>>(x, W_ih, b_ih, b_hh);
    gru_recurrent_kernel<<<NBLK, RT, REC_SMEM_BYTES>>>(h0, lens, W_hh, b_hh);
    gru_output_kernel<<<2048, 256>>>(lens, W_out, b_out, out);
}